// round 17
// baseline (speedup 1.0000x reference)
#include <cuda_runtime.h>
#include <cuda_fp16.h>
#include <math.h>
#include <stdint.h>

#define MTOT 8192      // n * T = 4 * 2048
#define DIM 1024
#define FFD 4096
#define TT 2048
#define NBATCH 4
#define NHEAD 16
#define HDIM 64
#define QKVSTR 3072

// ---------------- scratch (no allocs allowed) ----------------
__device__ __half g_Xp[MTOT * DIM];        // packed concat(kq,v), fp16 (A layout)
__device__ __half g_QKVh[MTOT * QKVSTR];   // fused K|Q|V output, fp16
__device__ float  g_Vres[MTOT * DIM];      // fp32 V projection (LN1 residual)
__device__ float  g_AO[MTOT * DIM];
__device__ float  g_H [MTOT * DIM];        // after LN1 (fp32)
__device__ __half g_Hp[MTOT * DIM];        // packed H (A layout, fp16)
__device__ __half g_Gp[MTOT * FFD];        // packed gelu out (A layout, fp16)
__device__ float  g_F [MTOT * DIM];
__device__ __half g_Wp[3 * DIM * DIM + 2 * FFD * DIM];  // packed weights (B layout, fp16)
__device__ float  g_bqkv[QKVSTR];

// ---------------- helpers ----------------
__device__ __forceinline__ void mma16(float* c, const unsigned* a, const unsigned* b) {
    asm volatile(
        "mma.sync.aligned.m16n8k16.row.col.f32.f16.f16.f32 "
        "{%0,%1,%2,%3}, {%4,%5,%6,%7}, {%8,%9}, {%0,%1,%2,%3};\n"
        : "+f"(c[0]), "+f"(c[1]), "+f"(c[2]), "+f"(c[3])
        : "r"(a[0]), "r"(a[1]), "r"(a[2]), "r"(a[3]), "r"(b[0]), "r"(b[1]));
}

__device__ __forceinline__ float h2f(float a, float b) {
    __half2 h = __floats2half2_rn(a, b);
    return __uint_as_float(*reinterpret_cast<unsigned*>(&h));
}
__device__ __forceinline__ unsigned h2u(float a, float b) {
    __half2 h = __floats2half2_rn(a, b);
    return *reinterpret_cast<unsigned*>(&h);
}

__device__ __forceinline__ uint32_t smem_u32(const void* p) {
    uint32_t a;
    asm("{ .reg .u64 t; cvta.to.shared.u64 t, %1; cvt.u32.u64 %0, t; }" : "=r"(a) : "l"(p));
    return a;
}
__device__ __forceinline__ void cp16(uint32_t dst, const void* src) {
    asm volatile("cp.async.cg.shared.global [%0], [%1], 16;" :: "r"(dst), "l"(src));
}

// ---------------- pack kernels ----------------
#define TSTR 36

__global__ void packA_concat_h(const float* __restrict__ kq, const float* __restrict__ vv,
                               __half* __restrict__ dst) {
    __shared__ float T[256 * TSTR];
    const int kt = blockIdx.x, mt = blockIdx.y, tid = threadIdx.x;
    const float* src = (kt < 16) ? kq : vv;
    const int kof = (kt < 16) ? kt * 32 : (kt - 16) * 32;
#pragma unroll
    for (int i = 0; i < 8; i++) {
        int idx = tid + 256 * i;
        int row = idx >> 3, q = idx & 7;
        float4 v = ((const float4*)(src + (size_t)(mt * 256 + row) * 512 + kof))[q];
        *(float4*)&T[row * TSTR + q * 4] = v;
    }
    __syncthreads();
    float4* d4 = (float4*)dst + (size_t)(mt * 32 + kt) * 1024;
#pragma unroll
    for (int j = 0; j < 4; j++) {
        int d = tid + 256 * j;
        int slot = d & 7, mblk = (d >> 3) & 15, tg = (d >> 7) & 3, ks = d >> 9;
        int gp = (slot - 2 * tg) & 7;
        int m = mblk * 16 + gp, k = ks * 16 + 2 * tg;
        float4 o;
        o.x = h2f(T[m * TSTR + k],           T[m * TSTR + k + 1]);
        o.y = h2f(T[(m + 8) * TSTR + k],     T[(m + 8) * TSTR + k + 1]);
        o.z = h2f(T[m * TSTR + k + 8],       T[m * TSTR + k + 9]);
        o.w = h2f(T[(m + 8) * TSTR + k + 8], T[(m + 8) * TSTR + k + 9]);
        d4[d] = o;
    }
}

__global__ void packB_h(const float* __restrict__ src, __half* __restrict__ dst, int K) {
    __shared__ float T[128 * TSTR];
    const int kt = blockIdx.x, nt = blockIdx.y, tid = threadIdx.x;
    const int NKt = K >> 5;
#pragma unroll
    for (int i = 0; i < 4; i++) {
        int idx = tid + 256 * i;
        int row = idx >> 3, q = idx & 7;
        float4 v = ((const float4*)(src + (size_t)(nt * 128 + row) * K + kt * 32))[q];
        *(float4*)&T[row * TSTR + q * 4] = v;
    }
    __syncthreads();
    float4* d4 = (float4*)dst + (size_t)(nt * NKt + kt) * 512;
#pragma unroll
    for (int j = 0; j < 2; j++) {
        int d = tid + 256 * j;
        int slot = d & 7, nblk = (d >> 3) & 7, tg = (d >> 6) & 3, ks = d >> 8;
        int gp = (slot - 2 * tg) & 7;
        int n = nblk * 16 + gp, k = ks * 16 + 2 * tg;
        float4 o;
        o.x = h2f(T[n * TSTR + k],           T[n * TSTR + k + 1]);
        o.y = h2f(T[n * TSTR + k + 8],       T[n * TSTR + k + 9]);
        o.z = h2f(T[(n + 8) * TSTR + k],     T[(n + 8) * TSTR + k + 1]);
        o.w = h2f(T[(n + 8) * TSTR + k + 8], T[(n + 8) * TSTR + k + 9]);
        d4[d] = o;
    }
}

__global__ void biascat(const float* __restrict__ bk, const float* __restrict__ bq,
                        const float* __restrict__ bv, float* __restrict__ dst) {
    int i = blockIdx.x * 256 + threadIdx.x;
    dst[i] = (i < 1024) ? bk[i] : (i < 2048 ? bq[i - 1024] : bv[i - 2048]);
}

// ---------------- packed fp16 GEMM, cp.async 4-stage pipeline ----------------
#define STGB 24576
#define GPSMEM (4 * STGB)

template<int GELU, int PACKOUT, int OUTH>
__global__ void __launch_bounds__(256, 1) gemm_pk(
    const float4* __restrict__ Apk, const float4* __restrict__ Bpk,
    const float* __restrict__ bias, float* __restrict__ C,
    float* __restrict__ V32, int N, int K)
{
    extern __shared__ float4 s4[];
    const int tid  = threadIdx.x;
    const int lane = tid & 31;
    const int warp = tid >> 5;
    const int g    = lane >> 2;
    const int tg   = lane & 3;
    const int wm   = (warp & 3) * 64;
    const int wn   = (warp >> 2) * 64;
    const int mt   = blockIdx.y;
    const int nt   = blockIdx.x;
    const int sgc  = (g + 2 * tg) & 7;
    const int NKt  = K >> 5;
    const uint32_t sbase = smem_u32(s4);

    float acc[4][8][4];
#pragma unroll
    for (int i = 0; i < 4; i++)
#pragma unroll
        for (int j = 0; j < 8; j++)
#pragma unroll
            for (int q = 0; q < 4; q++) acc[i][j][q] = 0.f;

#define FILLP(s, c) do { \
    const float4* As_ = Apk + ((size_t)mt * NKt + (c)) * 1024 + tid * 4; \
    const float4* Bs_ = Bpk + ((size_t)nt * NKt + (c)) * 512 + tid * 2; \
    uint32_t da_ = sbase + (s) * STGB + tid * 64; \
    uint32_t db_ = sbase + (s) * STGB + 16384 + tid * 32; \
    cp16(da_,      As_);     cp16(da_ + 16, As_ + 1); \
    cp16(da_ + 32, As_ + 2); cp16(da_ + 48, As_ + 3); \
    cp16(db_,      Bs_);     cp16(db_ + 16, Bs_ + 1); \
} while (0)

    FILLP(0, 0); asm volatile("cp.async.commit_group;" ::: "memory");
    FILLP(1, 1); asm volatile("cp.async.commit_group;" ::: "memory");
    FILLP(2, 2); asm volatile("cp.async.commit_group;" ::: "memory");

    for (int c = 0; c < NKt; c++) {
        asm volatile("cp.async.wait_group 2;" ::: "memory");
        __syncthreads();

        const float4* sa = s4 + (c & 3) * 1536;
        const float4* sb = sa + 1024;
#pragma unroll
        for (int ks = 0; ks < 2; ks++) {
            unsigned af[4][4], bf[8][2];
#pragma unroll
            for (int mi = 0; mi < 4; mi++) {
                float4 a4 = sa[ks * 512 + tg * 128 + ((wm >> 4) + mi) * 8 + sgc];
                af[mi][0] = __float_as_uint(a4.x);
                af[mi][1] = __float_as_uint(a4.y);
                af[mi][2] = __float_as_uint(a4.z);
                af[mi][3] = __float_as_uint(a4.w);
            }
#pragma unroll
            for (int j = 0; j < 4; j++) {
                float4 b4 = sb[ks * 256 + tg * 64 + ((wn >> 4) + j) * 8 + sgc];
                bf[2 * j][0]     = __float_as_uint(b4.x);
                bf[2 * j][1]     = __float_as_uint(b4.y);
                bf[2 * j + 1][0] = __float_as_uint(b4.z);
                bf[2 * j + 1][1] = __float_as_uint(b4.w);
            }
#pragma unroll
            for (int mi = 0; mi < 4; mi++)
#pragma unroll
                for (int ni = 0; ni < 8; ni++)
                    mma16(acc[mi][ni], af[mi], bf[ni]);
        }

        if (c + 3 < NKt) FILLP((c + 3) & 3, c + 3);
        asm volatile("cp.async.commit_group;" ::: "memory");
    }
#undef FILLP

    const int bm = mt * 256, bn = nt * 128;

    if (OUTH) {
        __half* Ch = (__half*)C;
#pragma unroll
        for (int ni = 0; ni < 8; ni++) {
            int n = bn + wn + ni * 8 + tg * 2;
            float b0 = bias[n], b1 = bias[n + 1];
            const bool isv = (n >= 2048);
#pragma unroll
            for (int mi = 0; mi < 4; mi++) {
                int m = bm + wm + mi * 16 + g;
                float v00 = acc[mi][ni][0] + b0;
                float v01 = acc[mi][ni][1] + b1;
                float v10 = acc[mi][ni][2] + b0;
                float v11 = acc[mi][ni][3] + b1;
                __half2 lo = __floats2half2_rn(v00, v01);
                __half2 hi = __floats2half2_rn(v10, v11);
                *(__half2*)&Ch[(size_t)m * N + n] = lo;
                *(__half2*)&Ch[(size_t)(m + 8) * N + n] = hi;
                if (isv) {
                    *(float2*)&V32[(size_t)m * DIM + n - 2048] = make_float2(v00, v01);
                    *(float2*)&V32[(size_t)(m + 8) * DIM + n - 2048] = make_float2(v10, v11);
                }
            }
        }
    } else if (!PACKOUT) {
#pragma unroll
        for (int ni = 0; ni < 8; ni++) {
            int n = bn + wn + ni * 8 + tg * 2;
            float b0 = bias[n], b1 = bias[n + 1];
#pragma unroll
            for (int mi = 0; mi < 4; mi++) {
                int m = bm + wm + mi * 16 + g;
                float v00 = acc[mi][ni][0] + b0;
                float v01 = acc[mi][ni][1] + b1;
                float v10 = acc[mi][ni][2] + b0;
                float v11 = acc[mi][ni][3] + b1;
                if (GELU) {
                    v00 = 0.5f * v00 * (1.f + erff(v00 * 0.7071067811865476f));
                    v01 = 0.5f * v01 * (1.f + erff(v01 * 0.7071067811865476f));
                    v10 = 0.5f * v10 * (1.f + erff(v10 * 0.7071067811865476f));
                    v11 = 0.5f * v11 * (1.f + erff(v11 * 0.7071067811865476f));
                }
                *(float2*)&C[(size_t)m * N + n] = make_float2(v00, v01);
                *(float2*)&C[(size_t)(m + 8) * N + n] = make_float2(v10, v11);
            }
        }
    } else {
        asm volatile("cp.async.wait_group 0;" ::: "memory");
        float* Cs = (float*)s4;
        const int NKo = N >> 5;
        float4* d4 = (float4*)C;
        for (int hf = 0; hf < 2; hf++) {
            __syncthreads();
            if ((warp >> 2) == hf) {
#pragma unroll
                for (int ni = 0; ni < 8; ni++) {
                    int ncol = ni * 8 + tg * 2;
                    int n = bn + hf * 64 + ncol;
                    float b0 = bias[n], b1 = bias[n + 1];
#pragma unroll
                    for (int mi = 0; mi < 4; mi++) {
                        int mr = wm + mi * 16 + g;
                        float v00 = acc[mi][ni][0] + b0;
                        float v01 = acc[mi][ni][1] + b1;
                        float v10 = acc[mi][ni][2] + b0;
                        float v11 = acc[mi][ni][3] + b1;
                        if (GELU) {
                            v00 = 0.5f * v00 * (1.f + erff(v00 * 0.7071067811865476f));
                            v01 = 0.5f * v01 * (1.f + erff(v01 * 0.7071067811865476f));
                            v10 = 0.5f * v10 * (1.f + erff(v10 * 0.7071067811865476f));
                            v11 = 0.5f * v11 * (1.f + erff(v11 * 0.7071067811865476f));
                        }
                        Cs[mr * 65 + ncol] = v00;
                        Cs[mr * 65 + ncol + 1] = v01;
                        Cs[(mr + 8) * 65 + ncol] = v10;
                        Cs[(mr + 8) * 65 + ncol + 1] = v11;
                    }
                }
            }
            __syncthreads();
#pragma unroll
            for (int t = 0; t < 8; t++) {
                int e = tid + 256 * t;
                int ktl = e >> 10, d = e & 1023;
                int slot = d & 7, mblk = (d >> 3) & 15, tgg = (d >> 7) & 3, ks = d >> 9;
                int gp = (slot - 2 * tgg) & 7;
                int m = mblk * 16 + gp;
                int col = ktl * 32 + ks * 16 + 2 * tgg;
                int ktg = ((bn + hf * 64) >> 5) + ktl;
                float4 o;
                o.x = h2f(Cs[m * 65 + col],           Cs[m * 65 + col + 1]);
                o.y = h2f(Cs[(m + 8) * 65 + col],     Cs[(m + 8) * 65 + col + 1]);
                o.z = h2f(Cs[m * 65 + col + 8],       Cs[m * 65 + col + 9]);
                o.w = h2f(Cs[(m + 8) * 65 + col + 8], Cs[(m + 8) * 65 + col + 9]);
                d4[((size_t)mt * NKo + ktg) * 1024 + d] = o;
            }
        }
    }
}

// ---------------- attention: fp16 mma flash, 64-row q tiles (proven R14) -------
#define PS2 36
#define SMEM_ATTN (24576 + 64 * PS2 * 4)

__global__ void __launch_bounds__(128, 3) attn_mma(
    const __half* __restrict__ QKV, float* __restrict__ AO)
{
    extern __shared__ char smc[];
    float4*   Ks4 = (float4*)smc;
    __half*   Vh  = (__half*)(smc + 8192);
    float4*   Vs4 = (float4*)(smc + 8192);
    unsigned* Qu  = (unsigned*)(smc + 16384);
    float4*   Qs4 = (float4*)(smc + 16384);
    unsigned* Ku  = (unsigned*)smc;
    unsigned* Pu  = (unsigned*)(smc + 24576);

    const int qb = blockIdx.x, h = blockIdx.y, b = blockIdx.z;
    const int tid = threadIdx.x;
    const int warp = tid >> 5, lane = tid & 31;
    const int g = lane >> 2, tg = lane & 3;
    const int sgc = (g + 2 * tg) & 7;
    const int qw0 = warp * 16;
    const size_t ib = ((size_t)b * TT) * QKVSTR + (size_t)h * HDIM;
    const size_t ob = ((size_t)b * TT) * DIM + (size_t)h * HDIM;
    const int q0 = qb * 64;

    for (int t = tid; t < 512; t += 128) {
        int row = t & 63, ch = t >> 6;
        const __half* src = QKV + 1024 + ib + (size_t)(q0 + row) * QKVSTR + ch * 8;
        uint4 u = *(const uint4*)src;
        unsigned p[4] = {u.x, u.y, u.z, u.w};
        int ks = ch >> 1, d8 = ch & 1;
        int mblk = row >> 4, gp = row & 7, hsel = (row >> 3) & 1;
#pragma unroll
        for (int t2 = 0; t2 < 4; t2++) {
            int quad = ks * 128 + t2 * 32 + mblk * 8 + ((gp + 2 * t2) & 7);
            Qu[quad * 4 + hsel + 2 * d8] = p[t2];
        }
    }
    __syncthreads();

    unsigned qf[4][4];
#pragma unroll
    for (int ks = 0; ks < 4; ks++) {
        float4 a4 = Qs4[ks * 128 + tg * 32 + warp * 8 + sgc];
        qf[ks][0] = __float_as_uint(a4.x);
        qf[ks][1] = __float_as_uint(a4.y);
        qf[ks][2] = __float_as_uint(a4.z);
        qf[ks][3] = __float_as_uint(a4.w);
    }

    float o[8][4];
#pragma unroll
    for (int ni = 0; ni < 8; ni++)
#pragma unroll
        for (int q = 0; q < 4; q++) o[ni][q] = 0.f;
    float m0 = -INFINITY, m1 = -INFINITY, l0 = 0.f, l1 = 0.f;

    for (int jb = 0; jb <= qb; jb++) {
        __syncthreads();
        const int k0 = jb * 64;
        for (int t = tid; t < 512; t += 128) {
            int row = t & 63, ch = t >> 6;
            const __half* src = QKV + ib + (size_t)(k0 + row) * QKVSTR + ch * 8;
            uint4 u = *(const uint4*)src;
            unsigned p[4] = {u.x, u.y, u.z, u.w};
            int ks = ch >> 1, d8 = ch & 1;
            int nblk = row >> 4, gp = row & 7, hsel = (row >> 3) & 1;
#pragma unroll
            for (int t2 = 0; t2 < 4; t2++) {
                int quad = ks * 128 + t2 * 32 + nblk * 8 + ((gp + 2 * t2) & 7);
                Ku[quad * 4 + d8 + 2 * hsel] = p[t2];
            }
        }
        for (int t = tid; t < 512; t += 128) {
            int row = t & 63, ch = t >> 6;
            const __half* src = QKV + 2048 + ib + (size_t)(k0 + row) * QKVSTR + ch * 8;
            uint4 u = *(const uint4*)src;
            const __half* ah = (const __half*)&u;
            int ks = row >> 4, rr = row & 15;
            int tgv = (rr & 7) >> 1, d1 = row & 1, d8 = (rr >> 3) & 1;
            int nblk = ch >> 1, hsel = ch & 1;
            int he = d1 + 2 * d8 + 4 * hsel;
#pragma unroll
            for (int e = 0; e < 8; e++) {
                int quad = ks * 128 + tgv * 32 + nblk * 8 + ((e + 2 * tgv) & 7);
                Vh[quad * 8 + he] = ah[e];
            }
        }
        __syncthreads();

        float s[8][4];
#pragma unroll
        for (int ni = 0; ni < 8; ni++)
#pragma unroll
            for (int q = 0; q < 4; q++) s[ni][q] = 0.f;
#pragma unroll
        for (int ks = 0; ks < 4; ks++) {
#pragma unroll
            for (int j = 0; j < 4; j++) {
                float4 b4 = Ks4[ks * 128 + tg * 32 + j * 8 + sgc];
                unsigned blo[2] = {__float_as_uint(b4.x), __float_as_uint(b4.y)};
                unsigned bhi[2] = {__float_as_uint(b4.z), __float_as_uint(b4.w)};
                mma16(s[2 * j],     qf[ks], blo);
                mma16(s[2 * j + 1], qf[ks], bhi);
            }
        }

        if (jb == qb) {
#pragma unroll
            for (int ni = 0; ni < 8; ni++) {
                int c = ni * 8 + 2 * tg;
                if (c     > qw0 + g)     s[ni][0] = -INFINITY;
                if (c + 1 > qw0 + g)     s[ni][1] = -INFINITY;
                if (c     > qw0 + g + 8) s[ni][2] = -INFINITY;
                if (c + 1 > qw0 + g + 8) s[ni][3] = -INFINITY;
            }
        }

        float rx0 = -INFINITY, rx1 = -INFINITY;
#pragma unroll
        for (int ni = 0; ni < 8; ni++) {
            rx0 = fmaxf(rx0, fmaxf(s[ni][0], s[ni][1]));
            rx1 = fmaxf(rx1, fmaxf(s[ni][2], s[ni][3]));
        }
        rx0 = fmaxf(rx0, __shfl_xor_sync(0xffffffffu, rx0, 1));
        rx0 = fmaxf(rx0, __shfl_xor_sync(0xffffffffu, rx0, 2));
        rx1 = fmaxf(rx1, __shfl_xor_sync(0xffffffffu, rx1, 1));
        rx1 = fmaxf(rx1, __shfl_xor_sync(0xffffffffu, rx1, 2));

        float mn0 = fmaxf(m0, rx0), mn1 = fmaxf(m1, rx1);
        float al0 = __expf(m0 - mn0), al1 = __expf(m1 - mn1);
        float ps0 = 0.f, ps1 = 0.f;
#pragma unroll
        for (int ni = 0; ni < 8; ni++) {
            unsigned plo = h2u(__expf(s[ni][0] - mn0), __expf(s[ni][1] - mn0));
            unsigned phi = h2u(__expf(s[ni][2] - mn1), __expf(s[ni][3] - mn1));
            Pu[(qw0 + g) * PS2 + 4 * ni + tg]     = plo;
            Pu[(qw0 + g + 8) * PS2 + 4 * ni + tg] = phi;
            __half2 hl = *(__half2*)&plo;
            __half2 hh = *(__half2*)&phi;
            ps0 += __half2float(__low2half(hl)) + __half2float(__high2half(hl));
            ps1 += __half2float(__low2half(hh)) + __half2float(__high2half(hh));
        }
        ps0 += __shfl_xor_sync(0xffffffffu, ps0, 1);
        ps0 += __shfl_xor_sync(0xffffffffu, ps0, 2);
        ps1 += __shfl_xor_sync(0xffffffffu, ps1, 1);
        ps1 += __shfl_xor_sync(0xffffffffu, ps1, 2);
        l0 = l0 * al0 + ps0;
        l1 = l1 * al1 + ps1;
        m0 = mn0; m1 = mn1;
#pragma unroll
        for (int ni = 0; ni < 8; ni++) {
            o[ni][0] *= al0; o[ni][1] *= al0;
            o[ni][2] *= al1; o[ni][3] *= al1;
        }
        __syncwarp();

#pragma unroll
        for (int ks = 0; ks < 4; ks++) {
            unsigned pf[4];
            pf[0] = Pu[(qw0 + g) * PS2 + 8 * ks + tg];
            pf[1] = Pu[(qw0 + g + 8) * PS2 + 8 * ks + tg];
            pf[2] = Pu[(qw0 + g) * PS2 + 8 * ks + tg + 4];
            pf[3] = Pu[(qw0 + g + 8) * PS2 + 8 * ks + tg + 4];
#pragma unroll
            for (int j = 0; j < 4; j++) {
                float4 b4 = Vs4[ks * 128 + tg * 32 + j * 8 + sgc];
                unsigned blo[2] = {__float_as_uint(b4.x), __float_as_uint(b4.y)};
                unsigned bhi[2] = {__float_as_uint(b4.z), __float_as_uint(b4.w)};
                mma16(o[2 * j],     pf, blo);
                mma16(o[2 * j + 1], pf, bhi);
            }
        }
    }

    float i0 = 1.f / l0, i1 = 1.f / l1;
#pragma unroll
    for (int ni = 0; ni < 8; ni++) {
        size_t r0 = ob + (size_t)(q0 + qw0 + g) * DIM + ni * 8 + 2 * tg;
        size_t r1 = ob + (size_t)(q0 + qw0 + g + 8) * DIM + ni * 8 + 2 * tg;
        *(float2*)&AO[r0] = make_float2(o[ni][0] * i0, o[ni][1] * i0);
        *(float2*)&AO[r1] = make_float2(o[ni][2] * i1, o[ni][3] * i1);
    }
}

// ---------------- fused add + LayerNorm (+ optional packed fp16 output) ----------
// Each thread owns 4 CONSECUTIVE cols (float4). PACK=1 additionally emits Hp quads.
template<int PACK>
__global__ void __launch_bounds__(256) add_ln_kernel(
    const float* __restrict__ A, int strideA, const float* __restrict__ B,
    const float* __restrict__ g, const float* __restrict__ beta,
    float* __restrict__ out, __half* __restrict__ outp)
{
    const int row = blockIdx.x;
    const float* a = A + (size_t)row * strideA;
    const float* b = B + (size_t)row * DIM;
    const int tid = threadIdx.x;
    const int c0 = tid * 4;

    float4 av = *(const float4*)(a + c0);
    float4 bv = *(const float4*)(b + c0);
    float x[4] = {av.x + bv.x, av.y + bv.y, av.z + bv.z, av.w + bv.w};
    float s = x[0] + x[1] + x[2] + x[3];
    float s2 = x[0]*x[0] + x[1]*x[1] + x[2]*x[2] + x[3]*x[3];
#pragma unroll
    for (int off = 16; off; off >>= 1) {
        s  += __shfl_down_sync(0xffffffffu, s,  off);
        s2 += __shfl_down_sync(0xffffffffu, s2, off);
    }
    __shared__ float ss[8], ss2[8];
    __shared__ float s_mean, s_inv;
    int w = tid >> 5;
    if ((tid & 31) == 0) { ss[w] = s; ss2[w] = s2; }
    __syncthreads();
    if (tid == 0) {
        float S = 0.f, S2 = 0.f;
#pragma unroll
        for (int i = 0; i < 8; i++) { S += ss[i]; S2 += ss2[i]; }
        float mu = S * (1.f / DIM);
        float var = S2 * (1.f / DIM) - mu * mu;
        s_mean = mu;
        s_inv = rsqrtf(var + 1e-5f);
    }
    __syncthreads();
    float mu = s_mean, iv = s_inv;
    float v[4];
#pragma unroll
    for (int i = 0; i < 4; i++)
        v[i] = (x[i] - mu) * iv * g[c0 + i] + beta[c0 + i];
    *(float4*)(out + (size_t)row * DIM + c0) = make_float4(v[0], v[1], v[2], v[3]);

    if (PACK) {
        int mt = row >> 8, mr = row & 255;
        int mblk = mr >> 4, gp = mr & 7, hsel = (mr >> 3) & 1;
        int kt = c0 >> 5;
        unsigned* du = (unsigned*)outp + ((size_t)(mt * 32 + kt) * 1024) * 4;
#pragma unroll
        for (int pr = 0; pr < 2; pr++) {
            int k = (c0 & 31) + 2 * pr;
            int ks = k >> 4, rem = k & 15;
            int t2 = (rem & 7) >> 1, d8 = rem >> 3;
            int quad = ks * 512 + t2 * 128 + mblk * 8 + ((gp + 2 * t2) & 7);
            du[quad * 4 + hsel + 2 * d8] = h2u(v[2 * pr], v[2 * pr + 1]);
        }
    }
}

// ---------------- host ----------------
extern "C" void kernel_launch(void* const* d_in, const int* in_sizes, int n_in,
                              void* d_out, int out_size)
{
    const float* kq  = (const float*)d_in[0];
    const float* v   = (const float*)d_in[1];
    const float* Wk  = (const float*)d_in[2];
    const float* bk  = (const float*)d_in[3];
    const float* Wq  = (const float*)d_in[4];
    const float* bq  = (const float*)d_in[5];
    const float* Wv  = (const float*)d_in[6];
    const float* bv  = (const float*)d_in[7];
    const float* W1  = (const float*)d_in[8];
    const float* b1  = (const float*)d_in[9];
    const float* W2  = (const float*)d_in[10];
    const float* b2  = (const float*)d_in[11];
    const float* g1  = (const float*)d_in[12];
    const float* be1 = (const float*)d_in[13];
    const float* g2  = (const float*)d_in[14];
    const float* be2 = (const float*)d_in[15];
    float* out = (float*)d_out;

    __half *Xp, *QKVh, *Hp, *Gp, *Wp;
    float *Vres, *AO, *Hh, *F, *bqkv;
    cudaGetSymbolAddress((void**)&Xp,   g_Xp);
    cudaGetSymbolAddress((void**)&QKVh, g_QKVh);
    cudaGetSymbolAddress((void**)&Vres, g_Vres);
    cudaGetSymbolAddress((void**)&AO,   g_AO);
    cudaGetSymbolAddress((void**)&Hh,   g_H);
    cudaGetSymbolAddress((void**)&Hp,   g_Hp);
    cudaGetSymbolAddress((void**)&Gp,   g_Gp);
    cudaGetSymbolAddress((void**)&F,    g_F);
    cudaGetSymbolAddress((void**)&Wp,   g_Wp);
    cudaGetSymbolAddress((void**)&bqkv, g_bqkv);

    __half* pW1 = Wp + 3 * DIM * DIM;
    __half* pW2 = Wp + 3 * DIM * DIM + (size_t)FFD * DIM;

    cudaFuncSetAttribute(gemm_pk<0, 0, 0>, cudaFuncAttributeMaxDynamicSharedMemorySize, GPSMEM);
    cudaFuncSetAttribute(gemm_pk<1, 1, 0>, cudaFuncAttributeMaxDynamicSharedMemorySize, GPSMEM);
    cudaFuncSetAttribute(gemm_pk<0, 0, 1>, cudaFuncAttributeMaxDynamicSharedMemorySize, GPSMEM);
    cudaFuncSetAttribute(attn_mma, cudaFuncAttributeMaxDynamicSharedMemorySize, SMEM_ATTN);

    // pack inputs (fp16)
    packA_concat_h<<<dim3(DIM / 32, MTOT / 256), 256>>>(kq, v, Xp);
    packB_h<<<dim3(DIM / 32, DIM / 128), 256>>>(Wk, Wp, DIM);
    packB_h<<<dim3(DIM / 32, DIM / 128), 256>>>(Wq, Wp + DIM * DIM, DIM);
    packB_h<<<dim3(DIM / 32, DIM / 128), 256>>>(Wv, Wp + 2 * DIM * DIM, DIM);
    packB_h<<<dim3(DIM / 32, FFD / 128), 256>>>(W1, pW1, DIM);
    packB_h<<<dim3(FFD / 32, DIM / 128), 256>>>(W2, pW2, FFD);
    biascat<<<QKVSTR / 256, 256>>>(bk, bq, bv, bqkv);

    // fused QKV GEMM -> fp16 QKV + fp32 V slice
    gemm_pk<0, 0, 1><<<dim3(QKVSTR / 128, MTOT / 256), 256, GPSMEM>>>(
        (const float4*)Xp, (const float4*)Wp, bqkv, (float*)QKVh, Vres, QKVSTR, DIM);

    attn_mma<<<dim3(TT / 64, NHEAD, NBATCH), 128, SMEM_ATTN>>>(QKVh, AO);

    // LN1 fused with packing of H
    add_ln_kernel<1><<<MTOT, 256>>>(Vres, DIM, AO, g1, be1, Hh, Hp);

    gemm_pk<1, 1, 0><<<dim3(FFD / 128, MTOT / 256), 256, GPSMEM>>>(
        (const float4*)Hp, (const float4*)pW1, b1, (float*)Gp, nullptr, FFD, DIM);
    gemm_pk<0, 0, 0><<<dim3(DIM / 128, MTOT / 256), 256, GPSMEM>>>(
        (const float4*)Gp, (const float4*)pW2, b2, F, nullptr, DIM, FFD);

    add_ln_kernel<0><<<MTOT, 256>>>(Hh, DIM, F, g2, be2, out, nullptr);
}